// round 4
// baseline (speedup 1.0000x reference)
#include <cuda_runtime.h>
#include <cuda_fp16.h>
#include <cstdint>

// ============================================================================
// out[b,l,d] = sum_{i,j} x0[b,i,d]*x1[b,j,d]*filters[i*64+j, l]
// B=2048, F1=F2=64, D=16, L=16.
//
// GEMM view: z[m,(i,l)] = sum_j x1[m,j] * W[(i,l),j], m=(b,d), then
// out[m,l] = sum_i x0[m,i] * z[m,(i,l)] in an fp32 register epilogue.
// Tensor path: legacy mma.sync.m16n8k16 (sm_100 non-'a' target: no tcgen05).
// W is the A operand (rows = 16 l's of one i), x1 is the B operand (cols = m).
// Precision: x1 in fp16, W split hi + lo*2^11 (2 MMA passes) -> rel_err ~2.5e-4.
// ============================================================================

// Pre-arranged W fragment image: [pass(2)][i(64)][kstep(4)][lane(32)] x 16B.
// Each 16B = thread-lane's {a0,a1,a2,a3} for mma.m16n8k16 (A row-major 16x16).
__device__ __align__(16) uint4 g_Wfrag[2 * 64 * 4 * 32];

__device__ __forceinline__ uint32_t pack_half2(float a, float b) {
    __half2 h = __floats2half2_rn(a, b);   // .x (low 16b) = a, .y = b
    return *(uint32_t*)&h;
}

__device__ __forceinline__ void mma16816(float c[4], const uint4& a, const uint2& b) {
    asm volatile(
        "mma.sync.aligned.m16n8k16.row.col.f32.f16.f16.f32 "
        "{%0,%1,%2,%3}, {%4,%5,%6,%7}, {%8,%9}, {%0,%1,%2,%3};\n"
        : "+f"(c[0]), "+f"(c[1]), "+f"(c[2]), "+f"(c[3])
        : "r"(a.x), "r"(a.y), "r"(a.z), "r"(a.w), "r"(b.x), "r"(b.y));
}

// ---------------------------------------------------------- prep kernel -----
// Build g_Wfrag. A-fragment mapping (m16k16, row-major), lane = 4*gid + q:
//   reg0 = {A[gid][2q],   A[gid][2q+1]}    reg1 = {A[gid+8][2q],   A[gid+8][2q+1]}
//   reg2 = {A[gid][2q+8], A[gid][2q+9]}    reg3 = {A[gid+8][2q+8], A[gid+8][2q+9]}
// A row = l value; A col = k = j (global j = 16*kstep + local).
// pass 0 = fp16(W); pass 1 = (W - hi) * 2^11 (kept normal in fp16).
__global__ void prep_w_kernel(const float* __restrict__ filters) {
    int idx  = blockIdx.x * 256 + threadIdx.x;    // 16384 total
    int pass = idx >> 13;
    int i    = (idx >> 7) & 63;
    int t    = (idx >> 5) & 3;
    int lane = idx & 31;
    int gid = lane >> 2, q = lane & 3;
    int k0 = t * 16 + q * 2;
    int l0 = gid, l1 = gid + 8;

    float e[8];
    int ls[8] = {l0, l0, l1, l1, l0, l0, l1, l1};
    int ks[8] = {k0, k0 + 1, k0, k0 + 1, k0 + 8, k0 + 9, k0 + 8, k0 + 9};
    #pragma unroll
    for (int j = 0; j < 8; ++j)
        e[j] = filters[(i * 64 + ks[j]) * 16 + ls[j]];

    uint32_t r[4];
    #pragma unroll
    for (int j = 0; j < 4; ++j) {
        float v0 = e[j * 2], v1 = e[j * 2 + 1];
        if (pass == 1) {
            float h0 = __half2float(__float2half(v0));
            float h1 = __half2float(__float2half(v1));
            v0 = (v0 - h0) * 2048.0f;
            v1 = (v1 - h1) * 2048.0f;
        }
        r[j] = pack_half2(v0, v1);
    }
    g_Wfrag[idx] = make_uint4(r[0], r[1], r[2], r[3]);
}

// ------------------------------------------------------------ main kernel ---
// SMEM: x1B (16KB) | x0e (32KB) | warp partial buffers (68KB, staging overlay)
static constexpr int SM_X1B  = 0;        // 2048 x uint2  (B fragments)
static constexpr int SM_X0E  = 16384;    // 4096 x float2 (x0 epilogue pairs)
static constexpr int SM_WB   = 49152;    // 8 warps x 2176 floats (padded 16x136)
static constexpr int SM_RAW  = SM_WB;    // 32KB staging overlay (pre-mainloop)
static constexpr int WB_WARP = 2176;     // floats per warp partial buffer
static constexpr int SMEM_TOTAL = SM_WB + 8 * WB_WARP * 4;   // 118784

__global__ __launch_bounds__(256, 1) void fm_main_kernel(
    const float* __restrict__ x0g,
    const float* __restrict__ x1g,
    float* __restrict__ outg)
{
    extern __shared__ __align__(16) unsigned char smem[];
    uint2*  x1B  = (uint2*)(smem + SM_X1B);
    float2* x0e  = (float2*)(smem + SM_X0E);
    float*  wb   = (float*)(smem + SM_WB);
    float4* raw4 = (float4*)(smem + SM_RAW);
    float*  raw  = (float*)(smem + SM_RAW);

    int tid = threadIdx.x;
    int w = tid >> 5, lane = tid & 31;
    int gid = lane >> 2, q = lane & 3;
    int bbase = blockIdx.x * 8;   // 8 b's -> 128 (b,d) rows per CTA

    // Prefetch W fragments for g=0 (i = w) while staging runs.
    uint4 curh[4], curl[4];
    #pragma unroll
    for (int t = 0; t < 4; ++t) {
        curh[t] = g_Wfrag[(w * 4 + t) * 32 + lane];
        curl[t] = g_Wfrag[((64 + w) * 4 + t) * 32 + lane];
    }

    // ---- stage x1 slab (8 b x 64 j x 16 d) coalesced, then build B frags ----
    const float4* x1s = (const float4*)(x1g + (size_t)bbase * 1024);
    for (int e = tid; e < 2048; e += 256) raw4[e] = x1s[e];
    __syncthreads();
    // B fragment (mc, t, lane): {x1[r][k0], [k0+1], [k0+8], [k0+9]},
    // r = mc*8 + gid (the n8 dim = m rows), k0 = 16t + 2q.
    for (int e = tid; e < 2048; e += 256) {
        int mc = e >> 7, t = (e >> 5) & 3, ln = e & 31;
        int g2 = ln >> 2, q2 = ln & 3;
        int r = mc * 8 + g2;
        int bl = r >> 4, d = r & 15;
        int k0 = t * 16 + q2 * 2;
        const float* base = raw + bl * 1024 + d;
        float f0 = base[k0 * 16];
        float f1 = base[(k0 + 1) * 16];
        float f2 = base[(k0 + 8) * 16];
        float f3 = base[(k0 + 9) * 16];
        x1B[e] = make_uint2(pack_half2(f0, f1), pack_half2(f2, f3));
    }
    __syncthreads();

    // ---- stage x0 slab, build epilogue pairs x0e[i*64 + mc*4 + q] ----
    const float4* x0s = (const float4*)(x0g + (size_t)bbase * 1024);
    for (int e = tid; e < 2048; e += 256) raw4[e] = x0s[e];
    __syncthreads();
    for (int e = tid; e < 4096; e += 256) {
        int i = e >> 6, mc = (e >> 2) & 15, q2 = e & 3;
        int m0 = mc * 8 + q2 * 2;
        int bl = m0 >> 4, d = m0 & 15;     // m0 even -> m0+1 same b
        const float* base = raw + bl * 1024 + i * 16 + d;
        x0e[e] = make_float2(base[0], base[1]);
    }
    __syncthreads();

    // ---- main loop: 8 i-groups; warp w handles i = 8g + w ----
    float acc[16][4];
    #pragma unroll
    for (int mc = 0; mc < 16; ++mc)
        #pragma unroll
        for (int j = 0; j < 4; ++j) acc[mc][j] = 0.0f;

    const float SLO = 1.0f / 2048.0f;
    uint4 nxth[4], nxtl[4];

    for (int g = 0; g < 8; ++g) {
        if (g < 7) {
            int in = (g + 1) * 8 + w;
            #pragma unroll
            for (int t = 0; t < 4; ++t) {
                nxth[t] = g_Wfrag[(in * 4 + t) * 32 + lane];
                nxtl[t] = g_Wfrag[((64 + in) * 4 + t) * 32 + lane];
            }
        }
        int i = g * 8 + w;
        const float2* x0p = x0e + i * 64 + q;

        #pragma unroll
        for (int mc = 0; mc < 16; ++mc) {
            uint2 b0 = x1B[(mc * 4 + 0) * 32 + lane];
            uint2 b1 = x1B[(mc * 4 + 1) * 32 + lane];
            uint2 b2 = x1B[(mc * 4 + 2) * 32 + lane];
            uint2 b3 = x1B[(mc * 4 + 3) * 32 + lane];
            float2 xv = x0p[mc * 4];
            float ch[4] = {0.f, 0.f, 0.f, 0.f};
            float cl[4] = {0.f, 0.f, 0.f, 0.f};
            mma16816(ch, curh[0], b0);  mma16816(cl, curl[0], b0);
            mma16816(ch, curh[1], b1);  mma16816(cl, curl[1], b1);
            mma16816(ch, curh[2], b2);  mma16816(cl, curl[2], b2);
            mma16816(ch, curh[3], b3);  mma16816(cl, curl[3], b3);
            // c0,c1: l=gid, m = mc*8+2q, +1 ; c2,c3: l=gid+8, same m.
            acc[mc][0] = fmaf(xv.x, fmaf(cl[0], SLO, ch[0]), acc[mc][0]);
            acc[mc][1] = fmaf(xv.y, fmaf(cl[1], SLO, ch[1]), acc[mc][1]);
            acc[mc][2] = fmaf(xv.x, fmaf(cl[2], SLO, ch[2]), acc[mc][2]);
            acc[mc][3] = fmaf(xv.y, fmaf(cl[3], SLO, ch[3]), acc[mc][3]);
        }
        if (g < 7) {
            #pragma unroll
            for (int t = 0; t < 4; ++t) { curh[t] = nxth[t]; curl[t] = nxtl[t]; }
        }
    }

    // ---- cross-warp reduction over i-partials ----
    float* wbw = wb + w * WB_WARP;
    #pragma unroll
    for (int mc = 0; mc < 16; ++mc) {
        int m0 = mc * 8 + q * 2;
        *(float2*)&wbw[gid * 136 + m0]       = make_float2(acc[mc][0], acc[mc][1]);
        *(float2*)&wbw[(gid + 8) * 136 + m0] = make_float2(acc[mc][2], acc[mc][3]);
    }
    __syncthreads();

    for (int o = tid; o < 2048; o += 256) {
        int bl = o >> 8, l = (o >> 4) & 15, d = o & 15;
        int m = bl * 16 + d;
        float s = 0.0f;
        #pragma unroll
        for (int ww = 0; ww < 8; ++ww)
            s += wb[ww * WB_WARP + l * 136 + m];
        outg[(size_t)(bbase + bl) * 256 + l * 16 + d] = s;   // coalesced
    }
}

// ------------------------------------------------------------------ launch --
extern "C" void kernel_launch(void* const* d_in, const int* in_sizes, int n_in,
                              void* d_out, int out_size) {
    const float* x0 = (const float*)d_in[0];
    const float* x1 = (const float*)d_in[1];
    const float* filters = (const float*)d_in[2];
    float* out = (float*)d_out;

    cudaFuncSetAttribute(fm_main_kernel,
                         cudaFuncAttributeMaxDynamicSharedMemorySize, SMEM_TOTAL);

    prep_w_kernel<<<64, 256>>>(filters);
    fm_main_kernel<<<256, 256, SMEM_TOTAL>>>(x0, x1, out);
}

// round 5
// speedup vs baseline: 1.5099x; 1.5099x over previous
#include <cuda_runtime.h>
#include <cuda_fp16.h>
#include <cstdint>

// ============================================================================
// out[b,l,d] = sum_{i,j} x0[b,i,d]*x1[b,j,d]*filters[i*64+j, l]
// B=2048, F1=F2=64, D=16, L=16.
//
// GEMM view: z[m,(i,l)] = sum_j x1[m,j] * W[(i,l),j], m=(b,d), then
// out[m,l] = sum_i x0[m,i] * z[m,(i,l)] in an fp32 register epilogue.
// mma.sync.m16n8k16, W as A operand (16 l-rows of one i), x1 as B operand.
// Single-pass fp16 (x1 fp16 error dominates; measured 2.1e-4 with exact W,
// predicted ~3e-4 with fp16 W — margin 3x under 1e-3).
// 2 CTAs/SM (<=128 regs, 84KB smem), 256 CTAs = one full wave.
// ============================================================================

// Pre-arranged W fragment image: [i(64)][kstep(4)][lane(32)] x 16B.
// Each 16B = lane's {a0,a1,a2,a3} for mma.m16n8k16 (A row-major 16x16).
__device__ __align__(16) uint4 g_Wfrag[64 * 4 * 32];

__device__ __forceinline__ uint32_t pack_half2(float a, float b) {
    __half2 h = __floats2half2_rn(a, b);   // .x (low 16b) = a, .y = b
    return *(uint32_t*)&h;
}

__device__ __forceinline__ void mma16816(float c[4], const uint4& a, const uint2& b) {
    asm volatile(
        "mma.sync.aligned.m16n8k16.row.col.f32.f16.f16.f32 "
        "{%0,%1,%2,%3}, {%4,%5,%6,%7}, {%8,%9}, {%0,%1,%2,%3};\n"
        : "+f"(c[0]), "+f"(c[1]), "+f"(c[2]), "+f"(c[3])
        : "r"(a.x), "r"(a.y), "r"(a.z), "r"(a.w), "r"(b.x), "r"(b.y));
}

// ---------------------------------------------------------- prep kernel -----
// A-fragment mapping (m16k16, row-major), lane = 4*gid + q:
//   reg0 = {A[gid][2q],   A[gid][2q+1]}    reg1 = {A[gid+8][2q],   A[gid+8][2q+1]}
//   reg2 = {A[gid][2q+8], A[gid][2q+9]}    reg3 = {A[gid+8][2q+8], A[gid+8][2q+9]}
// A row = l; A col = k = j (global j = 16*kstep + local).
__global__ void prep_w_kernel(const float* __restrict__ filters) {
    int idx  = blockIdx.x * 256 + threadIdx.x;    // 8192 total
    int i    = (idx >> 7) & 63;
    int t    = (idx >> 5) & 3;
    int lane = idx & 31;
    int gid = lane >> 2, q = lane & 3;
    int k0 = t * 16 + q * 2;
    int l0 = gid, l1 = gid + 8;

    float e[8];
    int ls[8] = {l0, l0, l1, l1, l0, l0, l1, l1};
    int ks[8] = {k0, k0 + 1, k0, k0 + 1, k0 + 8, k0 + 9, k0 + 8, k0 + 9};
    #pragma unroll
    for (int j = 0; j < 8; ++j)
        e[j] = filters[(i * 64 + ks[j]) * 16 + ls[j]];

    g_Wfrag[idx] = make_uint4(pack_half2(e[0], e[1]), pack_half2(e[2], e[3]),
                              pack_half2(e[4], e[5]), pack_half2(e[6], e[7]));
}

// ------------------------------------------------------------ main kernel ---
// SMEM: x1B (16KB) | x0e (32KB) | wb chunk buffers (36KB; staging overlay)
static constexpr int SM_X1B  = 0;        // 2048 x uint2  (B fragments)
static constexpr int SM_X0E  = 16384;    // 4096 x float2 (x0 epilogue pairs)
static constexpr int SM_WB   = 49152;    // 8 warps x 1152 floats (16 l x 72)
static constexpr int SM_RAW  = SM_WB;    // 32KB staging overlay (pre-mainloop)
static constexpr int WB_WARP = 1152;     // floats per warp chunk buffer
static constexpr int SMEM_TOTAL = SM_WB + 8 * WB_WARP * 4;   // 86016 (84KB)

__global__ __launch_bounds__(256, 2) void fm_main_kernel(
    const float* __restrict__ x0g,
    const float* __restrict__ x1g,
    float* __restrict__ outg)
{
    extern __shared__ __align__(16) unsigned char smem[];
    uint2*  x1B  = (uint2*)(smem + SM_X1B);
    float2* x0e  = (float2*)(smem + SM_X0E);
    float*  wb   = (float*)(smem + SM_WB);
    float4* raw4 = (float4*)(smem + SM_RAW);
    float*  raw  = (float*)(smem + SM_RAW);

    int tid = threadIdx.x;
    int w = tid >> 5, lane = tid & 31;
    int gid = lane >> 2, q = lane & 3;
    int bbase = blockIdx.x * 8;   // 8 b's -> 128 (b,d) rows per CTA

    // Prefetch W fragments for g=0 (i = w) while staging runs.
    uint4 cur[4];
    #pragma unroll
    for (int t = 0; t < 4; ++t)
        cur[t] = g_Wfrag[(w * 4 + t) * 32 + lane];

    // ---- stage x1 slab (8 b x 64 j x 16 d) coalesced, then build B frags ----
    const float4* x1s = (const float4*)(x1g + (size_t)bbase * 1024);
    for (int e = tid; e < 2048; e += 256) raw4[e] = x1s[e];
    __syncthreads();
    // B fragment (mc, t, lane): {x1[r][k0], [k0+1], [k0+8], [k0+9]},
    // r = mc*8 + gid (the n8 dim = m rows), k0 = 16t + 2q.
    for (int e = tid; e < 2048; e += 256) {
        int mc = e >> 7, t = (e >> 5) & 3, ln = e & 31;
        int g2 = ln >> 2, q2 = ln & 3;
        int r = mc * 8 + g2;
        int bl = r >> 4, d = r & 15;
        int k0 = t * 16 + q2 * 2;
        const float* base = raw + bl * 1024 + d;
        float f0 = base[k0 * 16];
        float f1 = base[(k0 + 1) * 16];
        float f2 = base[(k0 + 8) * 16];
        float f3 = base[(k0 + 9) * 16];
        x1B[e] = make_uint2(pack_half2(f0, f1), pack_half2(f2, f3));
    }
    __syncthreads();

    // ---- stage x0 slab, build epilogue pairs x0e[i*64 + mc*4 + q] ----
    const float4* x0s = (const float4*)(x0g + (size_t)bbase * 1024);
    for (int e = tid; e < 2048; e += 256) raw4[e] = x0s[e];
    __syncthreads();
    for (int e = tid; e < 4096; e += 256) {
        int i = e >> 6, mc = (e >> 2) & 15, q2 = e & 3;
        int m0 = mc * 8 + q2 * 2;
        int bl = m0 >> 4, d = m0 & 15;     // m0 even -> m0+1 same b
        const float* base = raw + bl * 1024 + i * 16 + d;
        x0e[e] = make_float2(base[0], base[1]);
    }
    __syncthreads();

    // ---- main loop: 8 i-groups; warp w handles i = 8g + w ----
    float acc[16][4];
    #pragma unroll
    for (int mc = 0; mc < 16; ++mc)
        #pragma unroll
        for (int j = 0; j < 4; ++j) acc[mc][j] = 0.0f;

    uint4 nxt[4];
    for (int g = 0; g < 8; ++g) {
        if (g < 7) {
            int in = (g + 1) * 8 + w;
            #pragma unroll
            for (int t = 0; t < 4; ++t)
                nxt[t] = g_Wfrag[(in * 4 + t) * 32 + lane];
        }
        int i = g * 8 + w;
        const float2* x0p = x0e + i * 64 + q;

        #pragma unroll
        for (int mc = 0; mc < 16; ++mc) {
            uint2 b0 = x1B[(mc * 4 + 0) * 32 + lane];
            uint2 b1 = x1B[(mc * 4 + 1) * 32 + lane];
            uint2 b2 = x1B[(mc * 4 + 2) * 32 + lane];
            uint2 b3 = x1B[(mc * 4 + 3) * 32 + lane];
            float2 xv = x0p[mc * 4];
            float c[4] = {0.f, 0.f, 0.f, 0.f};
            mma16816(c, cur[0], b0);
            mma16816(c, cur[1], b1);
            mma16816(c, cur[2], b2);
            mma16816(c, cur[3], b3);
            // c0,c1: l=gid, m = mc*8+2q, +1 ; c2,c3: l=gid+8, same m.
            acc[mc][0] = fmaf(xv.x, c[0], acc[mc][0]);
            acc[mc][1] = fmaf(xv.y, c[1], acc[mc][1]);
            acc[mc][2] = fmaf(xv.x, c[2], acc[mc][2]);
            acc[mc][3] = fmaf(xv.y, c[3], acc[mc][3]);
        }
        if (g < 7) {
            #pragma unroll
            for (int t = 0; t < 4; ++t) cur[t] = nxt[t];
        }
    }

    // ---- cross-warp reduction over i-partials, two mc-chunks of 8 ----
    #pragma unroll
    for (int chunk = 0; chunk < 2; ++chunk) {
        float* wbw = wb + w * WB_WARP;
        #pragma unroll
        for (int mcl = 0; mcl < 8; ++mcl) {
            int mc = chunk * 8 + mcl;
            int m0 = mcl * 8 + q * 2;           // local m in [0,64)
            *(float2*)&wbw[gid * 72 + m0]       = make_float2(acc[mc][0], acc[mc][1]);
            *(float2*)&wbw[(gid + 8) * 72 + m0] = make_float2(acc[mc][2], acc[mc][3]);
        }
        __syncthreads();

        for (int o = tid; o < 1024; o += 256) {
            int l = o >> 6, lm = o & 63;        // local m
            float s = 0.0f;
            #pragma unroll
            for (int ww = 0; ww < 8; ++ww)
                s += wb[ww * WB_WARP + l * 72 + lm];
            int m = chunk * 64 + lm;
            int bl = m >> 4, d = m & 15;
            outg[(size_t)(bbase + bl) * 256 + l * 16 + d] = s;
        }
        __syncthreads();
    }
}

// ------------------------------------------------------------------ launch --
extern "C" void kernel_launch(void* const* d_in, const int* in_sizes, int n_in,
                              void* d_out, int out_size) {
    const float* x0 = (const float*)d_in[0];
    const float* x1 = (const float*)d_in[1];
    const float* filters = (const float*)d_in[2];
    float* out = (float*)d_out;

    cudaFuncSetAttribute(fm_main_kernel,
                         cudaFuncAttributeMaxDynamicSharedMemorySize, SMEM_TOTAL);

    prep_w_kernel<<<32, 256>>>(filters);
    fm_main_kernel<<<256, 256, SMEM_TOTAL>>>(x0, x1, out);
}